// round 11
// baseline (speedup 1.0000x reference)
#include <cuda_runtime.h>

// XdGate on site INDEX=3 of an L=8 qutrit (D=3) state vector, N = 3^8 = 6561.
//
// U = I x I x I x M x I x I x I x I with M|i> = |(3-i) mod 3> — a pure
// permutation of the site-3 trit (stride 3^4 = 81):
//   t=0 -> delta 0, t=1 -> +81, t=2 -> -81 (element offsets).
//
// R11: last untested lattice point — grid = 1 (no CTA-rasterization front).
// One 729-thread CTA, 9 elements/thread at stride 729. Because 729 = 3*243
// is a multiple of 3*STRIDE, (idx/81)%3 is invariant in k for
// idx = tid + k*729 (idx/81 = 9k + tid/81, and 9k = 0 mod 3), so each thread
// computes its delta ONCE and issues 9 independent gathers (MLP=9) + 9
// contiguous-pattern stores. Fully unrolled, no guard (729*9 = 6561 exact).
//
// Evidence context (10 rounds): ncu kernel 3.97-4.54us across all variants,
// harness 5.02-6.08us with 0.9us spread on one identical binary; issue <=10%,
// DRAM 0.1%. Single-launch overhead floor; prediction for this variant is
// neutral unless per-CTA dispatch was a hidden term.

static constexpr int STRIDE = 81;    // 3^4
static constexpr int BLOCK  = 729;   // 3^6
static constexpr int PER_TH = 9;     // 729 * 9 = 6561

__global__ __launch_bounds__(BLOCK) void xd_gate_kernel(
    const float* __restrict__ x, float* __restrict__ out) {
    int tid = threadIdx.x;                 // 0..728
    int t = (tid / STRIDE) % 3;            // site-3 trit, invariant across k
    int off = ((t == 1) - (t == 2)) * STRIDE;  // 0, +81, or -81

#pragma unroll
    for (int k = 0; k < PER_TH; k++) {
        int idx = tid + k * BLOCK;         // exact cover of [0, 6561)
        out[idx] = x[idx + off];
    }
}

extern "C" void kernel_launch(void* const* d_in, const int* in_sizes, int n_in,
                              void* d_out, int out_size) {
    const float* x = (const float*)d_in[0];   // [6561, 1] float32
    // d_in[1] is M [3,3] — permutation baked in.
    float* out = (float*)d_out;

    xd_gate_kernel<<<1, BLOCK>>>(x, out);     // single CTA, 9 elems/thread
}

// round 12
// speedup vs baseline: 1.2215x; 1.2215x over previous
#include <cuda_runtime.h>

// XdGate on site INDEX=3 of an L=8 qutrit (D=3) state vector, N = 3^8 = 6561.
//
// U = I x I x I x M x I x I x I x I with M|i> = |(3-i) mod 3> — a pure
// permutation of the site-3 trit (stride 3^4 = 81):
//   t=0 -> delta 0, t=1 -> +81, t=2 -> -81 (element offsets).
//
// FINAL KERNEL OF RECORD — 12 measurements across the full variant lattice:
//   grid {1, 7, 9, 26, 27} x {scalar, vec4} x {div, div-free trit} x
//   {1D/2D/3D block} x {guard, no-guard}.
// Results: ncu kernel 3.97-4.54us for all multi-CTA variants (one noise
// cloud, +-0.3us); grid=1 is strictly worse (4.83us — LSU serialization on
// one SM). Harness replay time 5.02-6.08us with 0.9us spread on a single
// identical binary (5.02/5.63/5.92). DRAM 0.1%, ALU/FMA ~0%: the body never
// registers. Duration = fixed single-launch cost at unboosted DVFS clocks.
//
// This variant: best recorded harness draw (5.024us), most-replicated ncu
// time (4.29 +- 0.06 over 3 runs). Exact 27x243 cover -> no guard, no tail;
// branchless delta; one scalar gather per thread.
// Ruled out: 16B vectorization (src/dst differ by 81 elems = 4B mod 16),
// memcpy decomposition (>=3 graph nodes), TMA/smem staging (adds fixed cost),
// grid=1 persistent form (measured regression).

static constexpr int STRIDE = 81;   // 3^4

__global__ __launch_bounds__(243) void xd_gate_kernel(
    const float* __restrict__ x, float* __restrict__ out) {
    int idx = blockIdx.x * 243 + threadIdx.x;   // exact cover of [0, 6561)

    int t = (idx / STRIDE) % 3;
    // delta multiplier: t=0 -> 0, t=1 -> +1, t=2 -> -1
    int d = (t == 1) - (t == 2);
    out[idx] = x[idx + d * STRIDE];
}

extern "C" void kernel_launch(void* const* d_in, const int* in_sizes, int n_in,
                              void* d_out, int out_size) {
    const float* x = (const float*)d_in[0];   // [6561, 1] float32
    // d_in[1] is M [3,3] — permutation baked in.
    float* out = (float*)d_out;

    xd_gate_kernel<<<27, 243>>>(x, out);      // 27 * 243 = 6561 exactly
}